// round 4
// baseline (speedup 1.0000x reference)
#include <cuda_runtime.h>

// GlobalAttentionModule_7438883356930
//
// Key identity: out = (v[:,:,:,None] * softmax(score, axis=-1)).sum(-1)
//             = v * (softmax row-sum) = v
// since v is constant along the softmaxed axis. The whole [B,2C,N,N]
// pairwise attention-weight pipeline cancels. Output is exactly the value
// path: relu(GroupNorm_32(Wv @ feat + bv)).
//
// Shapes: B=2, C=128, N=512, groups=32 -> 4 channels/group, group size 4*512.
//
// One fused kernel: grid = B*32 blocks, one block per (batch, group).
//   - Wv rows for the block's 4 output channels staged in smem (2 KB).
//   - Each of 256 threads computes 4 channels x 2 consecutive n positions
//     (float2 coalesced feat loads), accumulators in registers.
//   - Block reduction for mean/var, then normalize + affine + relu + store.

#define C_DIM   128
#define N_DIM   512
#define B_DIM   2
#define GROUPS  32
#define CPG     4      // channels per group (C/GROUPS)
#define THREADS 256
#define EPS     1e-5f

__global__ __launch_bounds__(THREADS)
void fused_v_gn_relu(const float* __restrict__ feat,   // [B, C, N]
                     const float* __restrict__ Wv,     // [C, C] row-major (o, c)
                     const float* __restrict__ bv,     // [C]
                     const float* __restrict__ gamma,  // [C]
                     const float* __restrict__ beta,   // [C]
                     float* __restrict__ out)          // [B, C, N]
{
    const int b = blockIdx.x / GROUPS;
    const int g = blockIdx.x % GROUPS;
    const int t = threadIdx.x;

    __shared__ float w[CPG][C_DIM];
    __shared__ float red_s[THREADS / 32];
    __shared__ float red_ss[THREADS / 32];
    __shared__ float s_mean, s_rstd;

    // Stage the 4 weight rows for this group's output channels.
    #pragma unroll
    for (int i = t; i < CPG * C_DIM; i += THREADS) {
        const int cc = i / C_DIM;
        const int ci = i % C_DIM;
        w[cc][ci] = Wv[(g * CPG + cc) * C_DIM + ci];
    }
    __syncthreads();

    // GEMM: each thread -> 4 output channels x 2 consecutive n positions.
    const int n0 = 2 * t;                              // 0..510
    const float* fb = feat + (size_t)b * C_DIM * N_DIM + n0;

    float acc[CPG][2];
    #pragma unroll
    for (int cc = 0; cc < CPG; cc++) {
        const float bb = bv[g * CPG + cc];
        acc[cc][0] = bb;
        acc[cc][1] = bb;
    }

    #pragma unroll 8
    for (int ci = 0; ci < C_DIM; ci++) {
        const float2 x = *reinterpret_cast<const float2*>(fb + (size_t)ci * N_DIM);
        #pragma unroll
        for (int cc = 0; cc < CPG; cc++) {
            const float wv = w[cc][ci];          // smem broadcast
            acc[cc][0] = fmaf(wv, x.x, acc[cc][0]);
            acc[cc][1] = fmaf(wv, x.y, acc[cc][1]);
        }
    }

    // GroupNorm statistics over the group's 4*512 = 2048 values.
    float s = 0.f, ss = 0.f;
    #pragma unroll
    for (int cc = 0; cc < CPG; cc++) {
        #pragma unroll
        for (int k = 0; k < 2; k++) {
            const float v = acc[cc][k];
            s  += v;
            ss += v * v;
        }
    }
    #pragma unroll
    for (int o = 16; o > 0; o >>= 1) {
        s  += __shfl_xor_sync(0xffffffffu, s,  o);
        ss += __shfl_xor_sync(0xffffffffu, ss, o);
    }
    const int warp = t >> 5;
    const int lane = t & 31;
    if (lane == 0) { red_s[warp] = s; red_ss[warp] = ss; }
    __syncthreads();
    if (warp == 0) {
        s  = (lane < THREADS / 32) ? red_s[lane]  : 0.f;
        ss = (lane < THREADS / 32) ? red_ss[lane] : 0.f;
        #pragma unroll
        for (int o = 4; o > 0; o >>= 1) {
            s  += __shfl_xor_sync(0xffffffffu, s,  o);
            ss += __shfl_xor_sync(0xffffffffu, ss, o);
        }
        if (lane == 0) {
            const float inv = 1.0f / (float)(CPG * N_DIM);
            const float m   = s * inv;
            const float var = ss * inv - m * m;
            s_mean = m;
            s_rstd = rsqrtf(var + EPS);
        }
    }
    __syncthreads();

    const float m = s_mean;
    const float r = s_rstd;

    // Normalize + affine + relu + store (coalesced float2).
    #pragma unroll
    for (int cc = 0; cc < CPG; cc++) {
        const int c  = g * CPG + cc;
        const float ga = gamma[c] * r;
        const float be = beta[c];
        float2 o2;
        o2.x = fmaxf(fmaf(acc[cc][0] - m, ga, be), 0.f);
        o2.y = fmaxf(fmaf(acc[cc][1] - m, ga, be), 0.f);
        *reinterpret_cast<float2*>(out + ((size_t)b * C_DIM + c) * N_DIM + n0) = o2;
    }
}

extern "C" void kernel_launch(void* const* d_in, const int* in_sizes, int n_in,
                              void* d_out, int out_size)
{
    // metadata order:
    // 0 feat, 1 Wk, 2 bk, 3 Wq, 4 bq, 5 Wv, 6 bv, 7 gn_v_g, 8 gn_v_b,
    // 9 gn1_g, 10 gn1_b, 11 W1, 12 b1, 13 gn2_g, 14 gn2_b, 15 W2, 16 b2
    const float* feat  = (const float*)d_in[0];
    const float* Wv    = (const float*)d_in[5];
    const float* bv    = (const float*)d_in[6];
    const float* gn_g  = (const float*)d_in[7];
    const float* gn_b  = (const float*)d_in[8];
    float* out = (float*)d_out;

    fused_v_gn_relu<<<B_DIM * GROUPS, THREADS>>>(feat, Wv, bv, gn_g, gn_b, out);
}

// round 5
// speedup vs baseline: 1.3459x; 1.3459x over previous
#include <cuda_runtime.h>

// GlobalAttentionModule_7438883356930
//
// Identity: softmax row-sums are 1 and v is constant along the softmaxed axis,
// so out = relu(GroupNorm_32(Wv @ feat + bv)). (Verified: rel_err 8.8e-8.)
//
// Round 4 bottleneck: grid=64 -> occ 12.5%, issue 6.3% (latency exposed).
// Split N across 8 chunks per group -> 512 blocks, two kernels with
// deterministic partial-sum reduction (no float atomics).

#define C_DIM    128
#define N_DIM    512
#define B_DIM    2
#define GROUPS   32
#define CPG      4          // channels per group
#define NCHUNK   8          // n-chunks per group
#define CHUNK_N  (N_DIM / NCHUNK)   // 64
#define K1_THREADS 128
#define EPS      1e-5f

// Scratch (allocation-free rule: __device__ globals)
__device__ float  g_v[B_DIM * C_DIM * N_DIM];              // 512 KB
__device__ float2 g_part[B_DIM * GROUPS * NCHUNK];         // (sum, sumsq) per block

// ---------------------------------------------------------------------------
// K1: GEMM tile (4 out-ch x 64 n, k=128) + partial stats.
// Block = (bg, chunk). 128 threads: cc = t>>5 (channel), j = t&31 (float2 n).
// ---------------------------------------------------------------------------
__global__ __launch_bounds__(K1_THREADS)
void k1_gemm_part(const float* __restrict__ feat,   // [B, C, N]
                  const float* __restrict__ Wv,     // [C, C]
                  const float* __restrict__ bv)     // [C]
{
    const int bg    = blockIdx.x / NCHUNK;          // 0..63
    const int chunk = blockIdx.x % NCHUNK;
    const int b     = bg / GROUPS;
    const int g     = bg % GROUPS;
    const int t     = threadIdx.x;

    __shared__ float sx[C_DIM][CHUNK_N];            // 32 KB feat slice [k][n_local]
    __shared__ float w[CPG][C_DIM];                 // 2 KB weights
    __shared__ float red_s[K1_THREADS / 32];
    __shared__ float red_ss[K1_THREADS / 32];

    // Stage weights: 512 floats.
    {
        const float* wsrc = Wv + (size_t)(g * CPG) * C_DIM;
        #pragma unroll
        for (int i = t; i < CPG * C_DIM; i += K1_THREADS)
            w[i / C_DIM][i % C_DIM] = wsrc[i];
    }

    // Stage feat slice: 128 rows x 64 floats, as 2048 float4 (bulk MLP).
    {
        const float* fb = feat + (size_t)b * C_DIM * N_DIM + chunk * CHUNK_N;
        #pragma unroll
        for (int idx = t; idx < C_DIM * (CHUNK_N / 4); idx += K1_THREADS) {
            const int k   = idx >> 4;               // CHUNK_N/4 = 16 float4 per row
            const int nl4 = idx & 15;
            const float4 x = *reinterpret_cast<const float4*>(fb + (size_t)k * N_DIM + nl4 * 4);
            *reinterpret_cast<float4*>(&sx[k][nl4 * 4]) = x;
        }
    }
    __syncthreads();

    // GEMM: 1 channel x 1 float2-n per thread, k-loop over 128.
    const int cc = t >> 5;                          // 0..3
    const int j  = t & 31;                          // 0..31 (float2 index)

    const float bb = bv[g * CPG + cc];
    float ax = bb, ay = bb;

    #pragma unroll 8
    for (int k = 0; k < C_DIM; k++) {
        const float2 x = *reinterpret_cast<const float2*>(&sx[k][2 * j]);
        const float wv = w[cc][k];                  // uniform per warp (broadcast)
        ax = fmaf(wv, x.x, ax);
        ay = fmaf(wv, x.y, ay);
    }

    // Write v tile (coalesced float2).
    const int c  = g * CPG + cc;
    const int n0 = chunk * CHUNK_N + 2 * j;
    *reinterpret_cast<float2*>(g_v + ((size_t)b * C_DIM + c) * N_DIM + n0) =
        make_float2(ax, ay);

    // Partial stats (deterministic tree reduction).
    float s  = ax + ay;
    float ss = ax * ax + ay * ay;
    #pragma unroll
    for (int o = 16; o > 0; o >>= 1) {
        s  += __shfl_xor_sync(0xffffffffu, s,  o);
        ss += __shfl_xor_sync(0xffffffffu, ss, o);
    }
    const int warp = t >> 5, lane = t & 31;
    if (lane == 0) { red_s[warp] = s; red_ss[warp] = ss; }
    __syncthreads();
    if (t == 0) {
        float ts = 0.f, tss = 0.f;
        #pragma unroll
        for (int i = 0; i < K1_THREADS / 32; i++) { ts += red_s[i]; tss += red_ss[i]; }
        g_part[blockIdx.x] = make_float2(ts, tss);
    }
}

// ---------------------------------------------------------------------------
// K2: fold 8 partials -> mean/rstd, normalize + affine + relu + store.
// Same block mapping as K1.
// ---------------------------------------------------------------------------
__global__ __launch_bounds__(K1_THREADS)
void k2_norm(const float* __restrict__ gamma,
             const float* __restrict__ beta,
             float* __restrict__ out)
{
    const int bg    = blockIdx.x / NCHUNK;
    const int chunk = blockIdx.x % NCHUNK;
    const int b     = bg / GROUPS;
    const int g     = bg % GROUPS;
    const int t     = threadIdx.x;

    __shared__ float s_mean, s_rstd;

    if (t < 32) {
        float s = 0.f, ss = 0.f;
        if (t < NCHUNK) {
            const float2 p = g_part[bg * NCHUNK + t];
            s = p.x; ss = p.y;
        }
        #pragma unroll
        for (int o = 4; o > 0; o >>= 1) {
            s  += __shfl_xor_sync(0xffffffffu, s,  o);
            ss += __shfl_xor_sync(0xffffffffu, ss, o);
        }
        if (t == 0) {
            const float inv = 1.0f / (float)(CPG * N_DIM);
            const float m   = s * inv;
            const float var = ss * inv - m * m;
            s_mean = m;
            s_rstd = rsqrtf(var + EPS);
        }
    }
    __syncthreads();

    const float m = s_mean, r = s_rstd;

    const int cc = t >> 5;
    const int j  = t & 31;
    const int c  = g * CPG + cc;
    const int n0 = chunk * CHUNK_N + 2 * j;

    const float ga = gamma[c] * r;
    const float be = beta[c];

    const size_t off = ((size_t)b * C_DIM + c) * N_DIM + n0;
    const float2 v = *reinterpret_cast<const float2*>(g_v + off);
    float2 o2;
    o2.x = fmaxf(fmaf(v.x - m, ga, be), 0.f);
    o2.y = fmaxf(fmaf(v.y - m, ga, be), 0.f);
    *reinterpret_cast<float2*>(out + off) = o2;
}

extern "C" void kernel_launch(void* const* d_in, const int* in_sizes, int n_in,
                              void* d_out, int out_size)
{
    // 0 feat, 1 Wk, 2 bk, 3 Wq, 4 bq, 5 Wv, 6 bv, 7 gn_v_g, 8 gn_v_b, ...
    const float* feat = (const float*)d_in[0];
    const float* Wv   = (const float*)d_in[5];
    const float* bv   = (const float*)d_in[6];
    const float* gn_g = (const float*)d_in[7];
    const float* gn_b = (const float*)d_in[8];
    float* out = (float*)d_out;

    const int grid = B_DIM * GROUPS * NCHUNK;      // 512
    k1_gemm_part<<<grid, K1_THREADS>>>(feat, Wv, bv);
    k2_norm<<<grid, K1_THREADS>>>(gn_g, gn_b, out);
}

// round 6
// speedup vs baseline: 1.3499x; 1.0029x over previous
#include <cuda_runtime.h>
#include <cstdint>

// GlobalAttentionModule_7438883356930
//
// Identity: softmax row-sums are 1 and v is constant along the softmaxed axis,
// so out = relu(GroupNorm_32(Wv @ feat + bv)). (Verified: rel_err ~8e-8.)
//
// Round 5: fuse the two kernels with a thread-block CLUSTER. One cluster of 8
// blocks per (batch, group); partial GN stats exchanged via DSMEM, accumulators
// never leave registers. Removes the second launch and the 1 MB v round-trip.

#define C_DIM    128
#define N_DIM    512
#define B_DIM    2
#define GROUPS   32
#define CPG      4
#define NCHUNK   8                    // blocks per cluster = n-chunks per group
#define CHUNK_N  (N_DIM / NCHUNK)     // 64
#define THREADS  128
#define EPS      1e-5f

__device__ __forceinline__ uint32_t smem_u32(const void* p) {
    return (uint32_t)__cvta_generic_to_shared(p);
}

__global__ __launch_bounds__(THREADS) __cluster_dims__(NCHUNK, 1, 1)
void fused_cluster(const float* __restrict__ feat,   // [B, C, N]
                   const float* __restrict__ Wv,     // [C, C]
                   const float* __restrict__ bv,     // [C]
                   const float* __restrict__ gamma,  // [C]
                   const float* __restrict__ beta,   // [C]
                   float* __restrict__ out)          // [B, C, N]
{
    const int bg    = blockIdx.x / NCHUNK;   // (batch, group): clusters are 8 consecutive blocks
    const int chunk = blockIdx.x % NCHUNK;   // == cluster rank
    const int b     = bg / GROUPS;
    const int g     = bg % GROUPS;
    const int t     = threadIdx.x;

    __shared__ float  sx[C_DIM][CHUNK_N];    // 32 KB feat slice [k][n_local]
    __shared__ float  w[CPG][C_DIM];         // 2 KB weights
    __shared__ float  red_s[THREADS / 32];
    __shared__ float  red_ss[THREADS / 32];
    __shared__ float2 part;                  // this block's (sum, sumsq) — DSMEM-visible
    __shared__ float  s_mean, s_rstd;

    // ---- stage weights (512 floats) ----
    {
        const float* wsrc = Wv + (size_t)(g * CPG) * C_DIM;
        #pragma unroll
        for (int i = t; i < CPG * C_DIM; i += THREADS)
            w[i / C_DIM][i % C_DIM] = wsrc[i];
    }

    // ---- stage feat slice: 128 rows x 64 floats as float4 (bulk MLP) ----
    {
        const float* fb = feat + (size_t)b * C_DIM * N_DIM + chunk * CHUNK_N;
        #pragma unroll
        for (int idx = t; idx < C_DIM * (CHUNK_N / 4); idx += THREADS) {
            const int k   = idx >> 4;
            const int nl4 = idx & 15;
            const float4 x = *reinterpret_cast<const float4*>(fb + (size_t)k * N_DIM + nl4 * 4);
            *reinterpret_cast<float4*>(&sx[k][nl4 * 4]) = x;
        }
    }
    __syncthreads();

    // ---- GEMM: 1 out-channel x 1 float2-n per thread, k over 128 ----
    const int cc = t >> 5;                   // 0..3
    const int j  = t & 31;                   // 0..31
    const int c  = g * CPG + cc;

    const float bb = bv[c];
    float ax = bb, ay = bb;

    #pragma unroll 8
    for (int k = 0; k < C_DIM; k++) {
        const float2 x = *reinterpret_cast<const float2*>(&sx[k][2 * j]);
        const float wv = w[cc][k];           // uniform per warp (smem broadcast)
        ax = fmaf(wv, x.x, ax);
        ay = fmaf(wv, x.y, ay);
    }

    // Prefetch affine params now; latency hidden under reduction + cluster barrier.
    const float ga_raw = gamma[c];
    const float be     = beta[c];

    // ---- block-level partial stats (deterministic) ----
    float s  = ax + ay;
    float ss = ax * ax + ay * ay;
    #pragma unroll
    for (int o = 16; o > 0; o >>= 1) {
        s  += __shfl_xor_sync(0xffffffffu, s,  o);
        ss += __shfl_xor_sync(0xffffffffu, ss, o);
    }
    const int warp = t >> 5, lane = t & 31;
    if (lane == 0) { red_s[warp] = s; red_ss[warp] = ss; }
    __syncthreads();
    if (t == 0) {
        float ts = 0.f, tss = 0.f;
        #pragma unroll
        for (int i = 0; i < THREADS / 32; i++) { ts += red_s[i]; tss += red_ss[i]; }
        part = make_float2(ts, tss);
    }

    // ---- cluster barrier: t0's `part` store is release-ordered by arrive ----
    asm volatile("barrier.cluster.arrive.aligned;" ::: "memory");
    asm volatile("barrier.cluster.wait.aligned;"   ::: "memory");

    // ---- fold 8 peer partials via DSMEM (lanes 0..7, deterministic) ----
    if (t < 32) {
        float fs = 0.f, fss = 0.f;
        if (t < NCHUNK) {
            const uint32_t local = smem_u32(&part);
            uint32_t remote;
            asm("mapa.shared::cluster.u32 %0, %1, %2;"
                : "=r"(remote) : "r"(local), "r"(t));
            float px, py;
            asm volatile("ld.shared::cluster.v2.f32 {%0, %1}, [%2];"
                         : "=f"(px), "=f"(py) : "r"(remote));
            fs = px; fss = py;
        }
        #pragma unroll
        for (int o = 4; o > 0; o >>= 1) {
            fs  += __shfl_xor_sync(0xffffffffu, fs,  o);
            fss += __shfl_xor_sync(0xffffffffu, fss, o);
        }
        if (t == 0) {
            const float inv = 1.0f / (float)(CPG * N_DIM);
            const float m   = fs * inv;
            const float var = fss * inv - m * m;
            s_mean = m;
            s_rstd = rsqrtf(var + EPS);
        }
    }
    __syncthreads();

    // ---- normalize registers + affine + relu + store ----
    const float m  = s_mean;
    const float ga = ga_raw * s_rstd;
    const int   n0 = chunk * CHUNK_N + 2 * j;

    float2 o2;
    o2.x = fmaxf(fmaf(ax - m, ga, be), 0.f);
    o2.y = fmaxf(fmaf(ay - m, ga, be), 0.f);
    *reinterpret_cast<float2*>(out + ((size_t)b * C_DIM + c) * N_DIM + n0) = o2;

    // No CTA may exit while a peer might still read its DSMEM `part`.
    asm volatile("barrier.cluster.arrive.aligned;" ::: "memory");
    asm volatile("barrier.cluster.wait.aligned;"   ::: "memory");
}

extern "C" void kernel_launch(void* const* d_in, const int* in_sizes, int n_in,
                              void* d_out, int out_size)
{
    // 0 feat, 1 Wk, 2 bk, 3 Wq, 4 bq, 5 Wv, 6 bv, 7 gn_v_g, 8 gn_v_b, ...
    const float* feat = (const float*)d_in[0];
    const float* Wv   = (const float*)d_in[5];
    const float* bv   = (const float*)d_in[6];
    const float* gn_g = (const float*)d_in[7];
    const float* gn_b = (const float*)d_in[8];
    float* out = (float*)d_out;

    fused_cluster<<<B_DIM * GROUPS * NCHUNK, THREADS>>>(feat, Wv, bv, gn_g, gn_b, out);
}

// round 8
// speedup vs baseline: 1.3780x; 1.0208x over previous
#include <cuda_runtime.h>
#include <cstdint>

// GlobalAttentionModule_7438883356930
//
// Identity: softmax row-sums are 1 and v is constant along the softmaxed axis,
// so out = relu(GroupNorm_32(Wv @ feat + bv)). (Verified: rel_err ~8e-8.)
//
// R7: same cluster-of-8 stats exchange, but the block is reshaped for issue
// throughput: 256 threads = 4 k-quarters x (4 ch x 16 float4-n). float4
// mainloop (1.5 inst/output-update) + 4-way k-split (2x warps/SM at the same
// grid). Deterministic in-block combine + stats.

#define C_DIM    128
#define N_DIM    512
#define B_DIM    2
#define GROUPS   32
#define CPG      4
#define NCHUNK   8                    // blocks per cluster = n-chunks per group
#define CHUNK_N  (N_DIM / NCHUNK)     // 64
#define KSPLIT   4
#define KPART    (C_DIM / KSPLIT)     // 32
#define NF4      (CHUNK_N / 4)        // 16 float4 positions
#define THREADS  256                  // KSPLIT * CPG * NF4
#define EPS      1e-5f

__device__ __forceinline__ uint32_t smem_u32(const void* p) {
    return (uint32_t)__cvta_generic_to_shared(p);
}

__global__ __launch_bounds__(THREADS) __cluster_dims__(NCHUNK, 1, 1)
void fused_cluster(const float* __restrict__ feat,   // [B, C, N]
                   const float* __restrict__ Wv,     // [C, C]
                   const float* __restrict__ bv,     // [C]
                   const float* __restrict__ gamma,  // [C]
                   const float* __restrict__ beta,   // [C]
                   float* __restrict__ out)          // [B, C, N]
{
    const int bg    = blockIdx.x / NCHUNK;
    const int chunk = blockIdx.x % NCHUNK;   // == cluster rank
    const int b     = bg / GROUPS;
    const int g     = bg % GROUPS;
    const int t     = threadIdx.x;

    __shared__ float  sx[C_DIM][CHUNK_N];                // 32 KB feat slice [k][n_local]
    __shared__ float  w[CPG][C_DIM];                     // 2 KB weights
    __shared__ float4 scomb[KSPLIT - 1][CPG][NF4];       // 3 KB k-split partials
    __shared__ float  red_s[2], red_ss[2];
    __shared__ float2 part;                              // DSMEM-visible (sum, sumsq)
    __shared__ float  s_mean, s_rstd;

    // thread decomposition: q = k-quarter, cc = channel-in-group, j = float4 n index
    const int q  = t >> 6;          // 0..3
    const int cc = (t >> 4) & 3;    // 0..3
    const int j  = t & 15;          // 0..15

    // ---- stage weights (512 floats, 2 per thread) ----
    {
        const float* wsrc = Wv + (size_t)(g * CPG) * C_DIM;
        #pragma unroll
        for (int i = t; i < CPG * C_DIM; i += THREADS)
            w[i / C_DIM][i % C_DIM] = wsrc[i];
    }

    // ---- stage feat slice: 128 rows x 64 floats = 2048 float4, 8 per thread ----
    {
        const float* fb = feat + (size_t)b * C_DIM * N_DIM + chunk * CHUNK_N;
        #pragma unroll
        for (int idx = t; idx < C_DIM * NF4; idx += THREADS) {
            const int k   = idx >> 4;
            const int nl4 = idx & 15;
            const float4 x = *reinterpret_cast<const float4*>(fb + (size_t)k * N_DIM + nl4 * 4);
            *reinterpret_cast<float4*>(&sx[k][nl4 * 4]) = x;
        }
    }
    __syncthreads();

    // ---- GEMM: each thread does 32 k-iters for (cc, 4 n) ----
    float4 acc = make_float4(0.f, 0.f, 0.f, 0.f);
    {
        const int k0 = q * KPART;
        #pragma unroll 8
        for (int kk = 0; kk < KPART; kk++) {
            const int k = k0 + kk;
            const float4 x = *reinterpret_cast<const float4*>(&sx[k][4 * j]);
            const float wv = w[cc][k];               // warp-uniform smem broadcast
            acc.x = fmaf(wv, x.x, acc.x);
            acc.y = fmaf(wv, x.y, acc.y);
            acc.z = fmaf(wv, x.z, acc.z);
            acc.w = fmaf(wv, x.w, acc.w);
        }
    }

    // ---- deterministic k-split combine: quarters 1..3 -> smem, quarter 0 folds ----
    if (q > 0) scomb[q - 1][cc][j] = acc;
    __syncthreads();

    const int c = g * CPG + cc;
    float ga_raw = 0.f, be = 0.f;

    if (q == 0) {
        #pragma unroll
        for (int r = 0; r < KSPLIT - 1; r++) {
            const float4 p = scomb[r][cc][j];
            acc.x += p.x; acc.y += p.y; acc.z += p.z; acc.w += p.w;
        }
        const float bb = bv[c];
        acc.x += bb; acc.y += bb; acc.z += bb; acc.w += bb;

        // prefetch affine params; latency hides under reduction + cluster barrier
        ga_raw = gamma[c];
        be     = beta[c];

        // partial stats over this block's 4x64 values (warps 0..1 active)
        float s  = acc.x + acc.y + acc.z + acc.w;
        float ss = acc.x * acc.x + acc.y * acc.y + acc.z * acc.z + acc.w * acc.w;
        #pragma unroll
        for (int o = 16; o > 0; o >>= 1) {
            s  += __shfl_xor_sync(0xffffffffu, s,  o);
            ss += __shfl_xor_sync(0xffffffffu, ss, o);
        }
        const int warp = t >> 5, lane = t & 31;     // warp 0 or 1
        if (lane == 0) { red_s[warp] = s; red_ss[warp] = ss; }
    }
    __syncthreads();
    if (t == 0) {
        part = make_float2(red_s[0] + red_s[1], red_ss[0] + red_ss[1]);
    }

    // ---- cluster barrier (t0's `part` store release-ordered by arrive) ----
    asm volatile("barrier.cluster.arrive.aligned;" ::: "memory");
    asm volatile("barrier.cluster.wait.aligned;"   ::: "memory");

    // ---- fold 8 peer partials via DSMEM (lanes 0..7, deterministic) ----
    if (t < 32) {
        float fs = 0.f, fss = 0.f;
        if (t < NCHUNK) {
            const uint32_t local = smem_u32(&part);
            uint32_t remote;
            asm("mapa.shared::cluster.u32 %0, %1, %2;"
                : "=r"(remote) : "r"(local), "r"(t));
            float px, py;
            asm volatile("ld.shared::cluster.v2.f32 {%0, %1}, [%2];"
                         : "=f"(px), "=f"(py) : "r"(remote));
            fs = px; fss = py;
        }
        #pragma unroll
        for (int o = 4; o > 0; o >>= 1) {
            fs  += __shfl_xor_sync(0xffffffffu, fs,  o);
            fss += __shfl_xor_sync(0xffffffffu, fss, o);
        }
        if (t == 0) {
            const float inv = 1.0f / (float)(CPG * N_DIM);
            const float m   = fs * inv;
            const float var = fss * inv - m * m;
            s_mean = m;
            s_rstd = rsqrtf(var + EPS);
        }
    }
    __syncthreads();

    // ---- normalize + affine + relu + store (quarter-0 threads hold v) ----
    if (q == 0) {
        const float m  = s_mean;
        const float ga = ga_raw * s_rstd;
        const int   n0 = chunk * CHUNK_N + 4 * j;

        float4 o4;
        o4.x = fmaxf(fmaf(acc.x - m, ga, be), 0.f);
        o4.y = fmaxf(fmaf(acc.y - m, ga, be), 0.f);
        o4.z = fmaxf(fmaf(acc.z - m, ga, be), 0.f);
        o4.w = fmaxf(fmaf(acc.w - m, ga, be), 0.f);
        *reinterpret_cast<float4*>(out + ((size_t)b * C_DIM + c) * N_DIM + n0) = o4;
    }

    // no CTA may exit while a peer might still read its DSMEM `part`
    asm volatile("barrier.cluster.arrive.aligned;" ::: "memory");
    asm volatile("barrier.cluster.wait.aligned;"   ::: "memory");
}

extern "C" void kernel_launch(void* const* d_in, const int* in_sizes, int n_in,
                              void* d_out, int out_size)
{
    // 0 feat, 1 Wk, 2 bk, 3 Wq, 4 bq, 5 Wv, 6 bv, 7 gn_v_g, 8 gn_v_b, ...
    const float* feat = (const float*)d_in[0];
    const float* Wv   = (const float*)d_in[5];
    const float* bv   = (const float*)d_in[6];
    const float* gn_g = (const float*)d_in[7];
    const float* gn_b = (const float*)d_in[8];
    float* out = (float*)d_out;

    fused_cluster<<<B_DIM * GROUPS * NCHUNK, THREADS>>>(feat, Wv, bv, gn_g, gn_b, out);
}